// round 3
// baseline (speedup 1.0000x reference)
#include <cuda_runtime.h>

#define BS 32
#define LA 300
#define LB 1024
#define H  512
#define NROW (H*H)   // 262144 rows of W2d

// ---------------- scratch ----------------
__device__ float g_part[BS*8*H];
__device__ float g_bm[BS*H];
__device__ float g_T[(long)BS*NROW];     // [b][k*H+d]  33.5 MB

// ---------------- f32x2 helpers ----------------
__device__ __forceinline__ unsigned long long pack2(float x, float y) {
    unsigned long long r;
    unsigned int a = __float_as_uint(x), b = __float_as_uint(y);
    asm("mov.b64 %0, {%1, %2};" : "=l"(r) : "r"(a), "r"(b));
    return r;
}
__device__ __forceinline__ unsigned long long packdup(float x) {
    unsigned long long r;
    unsigned int a = __float_as_uint(x);
    asm("mov.b64 %0, {%1, %1};" : "=l"(r) : "r"(a));
    return r;
}
__device__ __forceinline__ unsigned long long fma2(unsigned long long a,
                                                   unsigned long long b,
                                                   unsigned long long c) {
    unsigned long long d;
    asm("fma.rn.f32x2 %0, %1, %2, %3;" : "=l"(d) : "l"(a), "l"(b), "l"(c));
    return d;
}
__device__ __forceinline__ float2 unpack2(unsigned long long v) {
    unsigned int a, b;
    asm("mov.b64 {%0, %1}, %2;" : "=r"(a), "=r"(b) : "l"(v));
    return make_float2(__uint_as_float(a), __uint_as_float(b));
}

// ---------------- kernel 1: b_mean ----------------
__global__ void k_bmean_part(const float* __restrict__ feat_b) {
    int chunk = blockIdx.x, b = blockIdx.y, d = threadIdx.x;
    const float* p = feat_b + ((long)b*LB + (long)chunk*128)*H + d;
    float s = 0.f;
    #pragma unroll 8
    for (int j = 0; j < 128; j++) s += p[(long)j*H];
    g_part[((long)b*8 + chunk)*H + d] = s;
}
__global__ void k_bmean_red() {
    long idx = (long)blockIdx.x*512 + threadIdx.x;
    long b = idx >> 9;
    long d = idx & 511;
    float s = 0.f;
    #pragma unroll
    for (int c = 0; c < 8; c++) s += g_part[(b*8 + c)*H + d];
    g_bm[idx] = s * (1.0f/1024.0f);
}

// ---------------- kernel 2: T[b][r] = sum_e W2d[r][e]*bm[b][e] ----------------
// 256 CTAs x 512 thr. CTA: 1024 rows. Thread: rows tid+{0,512} x 32 batches.
// smem: s_bm ULL[512][16] (64KB) + sW f32 [2][1024][20] (160KB) = 229376 B.
#define WGC 32            // number of K chunks (512/16)
#define SWS 20            // smem row stride in words (16 data + 4 pad)

__device__ __forceinline__ void wg_prefetch(const float* __restrict__ Wg, long r0,
                                            int kc, float* dst, int tid) {
    #pragma unroll
    for (int p = 0; p < 8; p++) {
        int idx = p*512 + tid;
        int row = idx >> 2, c = idx & 3;
        const float* g = Wg + (r0 + row)*H + kc*16 + c*4;
        unsigned saddr = (unsigned)__cvta_generic_to_shared(dst + row*SWS + c*4);
        asm volatile("cp.async.cg.shared.global [%0], [%1], 16;" :: "r"(saddr), "l"(g));
    }
    asm volatile("cp.async.commit_group;" ::: "memory");
}

__global__ void __launch_bounds__(512, 1) k_wgemm(const float* __restrict__ Wg) {
    extern __shared__ char smem_raw[];
    unsigned long long* s_bm = (unsigned long long*)smem_raw;    // [e][16]
    float* sW = (float*)(smem_raw + 65536);                      // [2][1024][SWS]
    int tid = threadIdx.x;
    long r0 = (long)blockIdx.x * 1024;

    for (int i = tid; i < 512*16; i += 512) {
        int e = i >> 4, n2 = i & 15;
        s_bm[i] = pack2(g_bm[(2*n2)*H + e], g_bm[(2*n2+1)*H + e]);
    }

    wg_prefetch(Wg, r0, 0, sW, tid);

    unsigned long long acc[2][16];
    #pragma unroll
    for (int i = 0; i < 2; i++)
        #pragma unroll
        for (int n2 = 0; n2 < 16; n2++) acc[i][n2] = 0ull;

    __syncthreads();   // bm ready

    for (int kc = 0; kc < WGC; kc++) {
        if (kc + 1 < WGC)
            wg_prefetch(Wg, r0, kc+1, sW + ((kc+1)&1)*1024*SWS, tid);
        if (kc + 1 < WGC) asm volatile("cp.async.wait_group 1;" ::: "memory");
        else              asm volatile("cp.async.wait_group 0;" ::: "memory");
        __syncthreads();

        const float* wb = sW + (kc&1)*1024*SWS;
        #pragma unroll
        for (int q = 0; q < 4; q++) {
            float4 w0 = *(const float4*)(wb + (long)tid*SWS + q*4);
            float4 w1 = *(const float4*)(wb + (long)(tid+512)*SWS + q*4);
            float l0[4] = {w0.x,w0.y,w0.z,w0.w};
            float l1[4] = {w1.x,w1.y,w1.z,w1.w};
            #pragma unroll
            for (int j = 0; j < 4; j++) {
                const unsigned long long* bp = s_bm + ((kc*16 + q*4 + j) << 4);
                unsigned long long wp0 = packdup(l0[j]);
                unsigned long long wp1 = packdup(l1[j]);
                #pragma unroll
                for (int n2 = 0; n2 < 16; n2++) {
                    unsigned long long bb = bp[n2];
                    acc[0][n2] = fma2(wp0, bb, acc[0][n2]);
                    acc[1][n2] = fma2(wp1, bb, acc[1][n2]);
                }
            }
        }
        __syncthreads();
    }

    // store transposed: g_T[b][r], consecutive lanes -> consecutive r (coalesced)
    #pragma unroll
    for (int i = 0; i < 2; i++) {
        long r = r0 + tid + i*512;
        #pragma unroll
        for (int n2 = 0; n2 < 16; n2++) {
            float2 p = unpack2(acc[i][n2]);
            g_T[(long)(2*n2  )*NROW + r] = p.x;
            g_T[(long)(2*n2+1)*NROW + r] = p.y;
        }
    }
}

// ---------------- kernel 3: fused = feat_a @ T^T (+bias +feat_a) ----------------
// tile 128x128x16, 256 thr (16x16), 8x8 microtile split as (ty*4,64+ty*4)x(tx*4,64+tx*4)
// -> all LDS.128 conflict-free (B lanes contiguous float4; A 2-address broadcast)
#define GBM 128
#define GBN 128
#define GPAD 132

__global__ void __launch_bounds__(256) k_gemm2(const float* __restrict__ A,
                                               const float* __restrict__ bias,
                                               float* __restrict__ out) {
    __shared__ float sA[16][GPAD];
    __shared__ float sB[16][GPAD];
    int b = blockIdx.z, rt = blockIdx.y, kt = blockIdx.x;
    int tid = threadIdx.x;
    int tx = tid & 15, ty = tid >> 4;
    int row0 = rt * GBM;
    const float* Ab = A + (long)b*LA*H;
    const float* Bb = g_T + (long)b*NROW + (long)kt*GBN*H;

    int lr = tid >> 2;        // 0..63
    int lc = tid & 3;         // float4 col

    float4 rA[2], rB[2];
    const float4 z4 = make_float4(0.f,0.f,0.f,0.f);

    auto ldg_chunk = [&](int kc) {
        #pragma unroll
        for (int h = 0; h < 2; h++) {
            int r = lr + h*64;
            int ar = row0 + r;
            rA[h] = (ar < LA) ? *(const float4*)(Ab + (long)ar*H + kc*16 + lc*4) : z4;
            rB[h] = *(const float4*)(Bb + (long)r*H + kc*16 + lc*4);
        }
    };
    auto sts_chunk = [&]() {
        #pragma unroll
        for (int h = 0; h < 2; h++) {
            int r = lr + h*64;
            sA[lc*4+0][r] = rA[h].x; sA[lc*4+1][r] = rA[h].y;
            sA[lc*4+2][r] = rA[h].z; sA[lc*4+3][r] = rA[h].w;
            sB[lc*4+0][r] = rB[h].x; sB[lc*4+1][r] = rB[h].y;
            sB[lc*4+2][r] = rB[h].z; sB[lc*4+3][r] = rB[h].w;
        }
    };

    unsigned long long acc[8][4];
    #pragma unroll
    for (int i = 0; i < 8; i++)
        #pragma unroll
        for (int j = 0; j < 4; j++) acc[i][j] = 0ull;

    ldg_chunk(0);
    sts_chunk();
    __syncthreads();

    for (int kc = 0; kc < 32; kc++) {
        if (kc + 1 < 32) ldg_chunk(kc+1);
        #pragma unroll
        for (int kk = 0; kk < 16; kk++) {
            float4 a0 = *(const float4*)&sA[kk][ty*4];
            float4 a1 = *(const float4*)&sA[kk][64 + ty*4];
            ulonglong2 b0 = *(const ulonglong2*)&sB[kk][tx*4];
            ulonglong2 b1 = *(const ulonglong2*)&sB[kk][64 + tx*4];
            float av[8] = {a0.x,a0.y,a0.z,a0.w, a1.x,a1.y,a1.z,a1.w};
            #pragma unroll
            for (int i = 0; i < 8; i++) {
                unsigned long long ap = packdup(av[i]);
                acc[i][0] = fma2(ap, b0.x, acc[i][0]);
                acc[i][1] = fma2(ap, b0.y, acc[i][1]);
                acc[i][2] = fma2(ap, b1.x, acc[i][2]);
                acc[i][3] = fma2(ap, b1.y, acc[i][3]);
            }
        }
        __syncthreads();
        if (kc + 1 < 32) {
            sts_chunk();
            __syncthreads();
        }
    }

    int k0a = kt*GBN + tx*4;
    int k0b = k0a + 64;
    const float4 bias0 = *(const float4*)(bias + k0a);
    const float4 bias1 = *(const float4*)(bias + k0b);
    #pragma unroll
    for (int i = 0; i < 8; i++) {
        int rloc = (i < 4) ? (ty*4 + i) : (64 + ty*4 + i - 4);
        int ar = row0 + rloc;
        if (ar < LA) {
            const float4 fa0 = *(const float4*)(Ab + (long)ar*H + k0a);
            const float4 fa1 = *(const float4*)(Ab + (long)ar*H + k0b);
            float2 p0 = unpack2(acc[i][0]), p1 = unpack2(acc[i][1]);
            float2 p2 = unpack2(acc[i][2]), p3 = unpack2(acc[i][3]);
            float4 o0 = make_float4(p0.x + bias0.x + fa0.x, p0.y + bias0.y + fa0.y,
                                    p1.x + bias0.z + fa0.z, p1.y + bias0.w + fa0.w);
            float4 o1 = make_float4(p2.x + bias1.x + fa1.x, p2.y + bias1.y + fa1.y,
                                    p3.x + bias1.z + fa1.z, p3.y + bias1.w + fa1.w);
            float* orow = out + ((long)b*LA + ar)*H;
            *(float4*)(orow + k0a) = o0;
            *(float4*)(orow + k0b) = o1;
        }
    }
}

// ---------------- kernel 4: LayerNorm in-place ----------------
__global__ void k_ln(const float* __restrict__ gamma, const float* __restrict__ beta,
                     float* __restrict__ out) {
    __shared__ float ssum[4], ssq[4];
    long row = blockIdx.x;
    int tid = threadIdx.x;
    float4* xr = reinterpret_cast<float4*>(out + row*H);
    float4 v = xr[tid];
    float s  = v.x + v.y + v.z + v.w;
    float sq = v.x*v.x + v.y*v.y + v.z*v.z + v.w*v.w;
    #pragma unroll
    for (int o = 16; o > 0; o >>= 1) {
        s  += __shfl_xor_sync(0xffffffffu, s,  o);
        sq += __shfl_xor_sync(0xffffffffu, sq, o);
    }
    int wid = tid >> 5;
    if ((tid & 31) == 0) { ssum[wid] = s; ssq[wid] = sq; }
    __syncthreads();
    float stot = ssum[0] + ssum[1] + ssum[2] + ssum[3];
    float sqtot = ssq[0] + ssq[1] + ssq[2] + ssq[3];
    float mu = stot * (1.0f/H);
    float var = sqtot * (1.0f/H) - mu*mu;
    float rstd = rsqrtf(var + 1e-5f);
    const float4 g4 = reinterpret_cast<const float4*>(gamma)[tid];
    const float4 b4 = reinterpret_cast<const float4*>(beta)[tid];
    v.x = (v.x - mu)*rstd*g4.x + b4.x;
    v.y = (v.y - mu)*rstd*g4.y + b4.y;
    v.z = (v.z - mu)*rstd*g4.z + b4.z;
    v.w = (v.w - mu)*rstd*g4.w + b4.w;
    xr[tid] = v;
}

// ---------------- launch ----------------
extern "C" void kernel_launch(void* const* d_in, const int* in_sizes, int n_in,
                              void* d_out, int out_size) {
    const float* feat_a = (const float*)d_in[0];
    const float* feat_b = (const float*)d_in[1];
    const float* W      = (const float*)d_in[2];
    const float* bias   = (const float*)d_in[3];
    const float* gamma  = (const float*)d_in[4];
    const float* beta   = (const float*)d_in[5];
    float* out = (float*)d_out;

    static bool attr_done = false;
    if (!attr_done) {
        cudaFuncSetAttribute(k_wgemm, cudaFuncAttributeMaxDynamicSharedMemorySize, 229376);
        attr_done = true;
    }

    k_bmean_part<<<dim3(8,32), 512>>>(feat_b);
    k_bmean_red<<<32, 512>>>();
    k_wgemm<<<256, 512, 229376>>>(W);
    k_gemm2<<<dim3(4,3,32), 256>>>(feat_a, bias, out);
    k_ln<<<9600, 128>>>(gamma, beta, out);
}

// round 5
// speedup vs baseline: 1.2448x; 1.2448x over previous
#include <cuda_runtime.h>
#include <cstdint>

#define BS 32
#define LA 300
#define LB 1024
#define H  512
#define NROW (H*H)   // 262144 rows of W2d

// ---------------- scratch ----------------
__device__ float g_part[BS*8*H];
__device__ float g_bm[BS*H];              // b_mean [b][e]
__device__ uint32_t g_bmfrag[64*4*32*2];  // tf32 B fragments [ks][nt][lane][2]  (64KB)
__device__ float g_T[(long)BS*NROW];      // [b][k*H+d]  33.5 MB

// ---------------- f32x2 helpers (gemm2) ----------------
__device__ __forceinline__ unsigned long long packdup(float x) {
    unsigned long long r;
    unsigned int a = __float_as_uint(x);
    asm("mov.b64 %0, {%1, %1};" : "=l"(r) : "r"(a));
    return r;
}
__device__ __forceinline__ unsigned long long fma2(unsigned long long a,
                                                   unsigned long long b,
                                                   unsigned long long c) {
    unsigned long long d;
    asm("fma.rn.f32x2 %0, %1, %2, %3;" : "=l"(d) : "l"(a), "l"(b), "l"(c));
    return d;
}
__device__ __forceinline__ float2 unpack2(unsigned long long v) {
    unsigned int a, b;
    asm("mov.b64 {%0, %1}, %2;" : "=r"(a), "=r"(b) : "l"(v));
    return make_float2(__uint_as_float(a), __uint_as_float(b));
}

// ---------------- tf32 helpers ----------------
__device__ __forceinline__ uint32_t f2tf(float f) {
    uint32_t r;
    asm("cvt.rna.tf32.f32 %0, %1;" : "=r"(r) : "f"(f));
    return r;
}
__device__ __forceinline__ void mma_tf32(float* c, uint32_t a0, uint32_t a1,
                                         uint32_t a2, uint32_t a3,
                                         uint32_t b0, uint32_t b1) {
    asm volatile("mma.sync.aligned.m16n8k8.row.col.f32.tf32.tf32.f32 "
                 "{%0,%1,%2,%3}, {%4,%5,%6,%7}, {%8,%9}, {%0,%1,%2,%3};"
                 : "+f"(c[0]), "+f"(c[1]), "+f"(c[2]), "+f"(c[3])
                 : "r"(a0), "r"(a1), "r"(a2), "r"(a3), "r"(b0), "r"(b1));
}

// ---------------- kernel 1: b_mean ----------------
__global__ void k_bmean_part(const float* __restrict__ feat_b) {
    int chunk = blockIdx.x, b = blockIdx.y, d = threadIdx.x;
    const float* p = feat_b + ((long)b*LB + (long)chunk*128)*H + d;
    float s = 0.f;
    #pragma unroll 8
    for (int j = 0; j < 128; j++) s += p[(long)j*H];
    g_part[((long)b*8 + chunk)*H + d] = s;
}
__global__ void k_bmean_red() {
    long idx = (long)blockIdx.x*512 + threadIdx.x;
    long b = idx >> 9, d = idx & 511;
    float s = 0.f;
    #pragma unroll
    for (int c = 0; c < 8; c++) s += g_part[(b*8 + c)*H + d];
    g_bm[idx] = s * (1.0f/1024.0f);
}

// ---------------- kernel 1b: B fragments (tf32, mma lane order) ----------------
// b0: k = ks*8 + tg,   n = nt*8 + group ;  b1: k += 4
__global__ void k_bfrag() {
    int idx = blockIdx.x*256 + threadIdx.x;     // 16384 total
    int j    = idx & 1;
    int lane = (idx >> 1) & 31;
    int nt   = (idx >> 6) & 3;
    int ks   = idx >> 8;
    int n = nt*8 + (lane >> 2);
    int k = ks*8 + (lane & 3) + 4*j;
    g_bmfrag[idx] = f2tf(g_bm[n*H + k]);
}

// ---------------- kernel 2: T[b][r] = W2d x bm^T via mma.sync tf32 ----------------
// CTA: 256 thr (8 warps), 128 rows. Warp: 16-row slab, N=32 (4 n-tiles), K=512 (64 ksteps).
// A fragments straight from gmem (sector-coalesced); B fragments LDS.64 conflict-free.
#define WM_SMEM (65536 + 16384)

__global__ void __launch_bounds__(256) k_wgemm_mma(const float* __restrict__ Wg) {
    extern __shared__ char smem[];
    uint2* sbf = (uint2*)smem;                  // [64*4*32]  B fragments
    float* sD  = (float*)(smem + 65536);        // [32][128]  epilogue staging

    int tid = threadIdx.x;
    int wid = tid >> 5, lane = tid & 31;
    int group = lane >> 2, tg = lane & 3;
    long r0 = (long)blockIdx.x * 128;
    int m0 = wid * 16;

    // cp.async the 64KB fragment blob (contiguous)
    {
        const char* src = (const char*)g_bmfrag;
        #pragma unroll
        for (int p = 0; p < 16; p++) {
            int i = p*256 + tid;
            unsigned dst = (unsigned)__cvta_generic_to_shared((char*)smem + i*16);
            asm volatile("cp.async.cg.shared.global [%0], [%1], 16;"
                         :: "r"(dst), "l"(src + (long)i*16));
        }
        asm volatile("cp.async.commit_group;" ::: "memory");
    }

    const float* A0 = Wg + (r0 + m0 + group)*H + tg;       // rows group / group+8
    const float* A1 = A0 + 8*H;

    float acc[4][4];
    #pragma unroll
    for (int i = 0; i < 4; i++)
        #pragma unroll
        for (int j = 0; j < 4; j++) acc[i][j] = 0.f;

    asm volatile("cp.async.wait_group 0;" ::: "memory");
    __syncthreads();

    #pragma unroll 4
    for (int ks = 0; ks < 64; ks++) {
        float f0 = __ldg(A0 + ks*8);
        float f2 = __ldg(A0 + ks*8 + 4);
        float f1 = __ldg(A1 + ks*8);
        float f3 = __ldg(A1 + ks*8 + 4);
        uint32_t a0 = f2tf(f0), a1 = f2tf(f1), a2 = f2tf(f2), a3 = f2tf(f3);
        const uint2* bb = sbf + (ks*4)*32 + lane;
        #pragma unroll
        for (int nt = 0; nt < 4; nt++) {
            uint2 b = bb[nt*32];
            mma_tf32(acc[nt], a0, a1, a2, a3, b.x, b.y);
        }
    }

    // epilogue: stage [n][rl] then coalesced store g_T[b][r]
    #pragma unroll
    for (int nt = 0; nt < 4; nt++) {
        int n0 = nt*8 + 2*tg;
        int rl = m0 + group;
        sD[(n0  )*128 + rl    ] = acc[nt][0];
        sD[(n0+1)*128 + rl    ] = acc[nt][1];
        sD[(n0  )*128 + rl + 8] = acc[nt][2];
        sD[(n0+1)*128 + rl + 8] = acc[nt][3];
    }
    __syncthreads();
    #pragma unroll
    for (int p = 0; p < 16; p++) {
        int i = p*256 + tid;
        int n = i >> 7, rl = i & 127;
        g_T[(long)n*NROW + r0 + rl] = sD[i];
    }
}

// ---------------- kernel 3: fused = feat_a @ T^T (+bias +feat_a)  [proven R3] ----
#define GBM 128
#define GBN 128
#define GPAD 132

__global__ void __launch_bounds__(256) k_gemm2(const float* __restrict__ A,
                                               const float* __restrict__ bias,
                                               float* __restrict__ out) {
    __shared__ float sA[16][GPAD];
    __shared__ float sB[16][GPAD];
    int b = blockIdx.z, rt = blockIdx.y, kt = blockIdx.x;
    int tid = threadIdx.x;
    int tx = tid & 15, ty = tid >> 4;
    int row0 = rt * GBM;
    const float* Ab = A + (long)b*LA*H;
    const float* Bb = g_T + (long)b*NROW + (long)kt*GBN*H;

    int lr = tid >> 2;
    int lc = tid & 3;

    float4 rA[2], rB[2];
    const float4 z4 = make_float4(0.f,0.f,0.f,0.f);

    auto ldg_chunk = [&](int kc) {
        #pragma unroll
        for (int h = 0; h < 2; h++) {
            int r = lr + h*64;
            int ar = row0 + r;
            rA[h] = (ar < LA) ? *(const float4*)(Ab + (long)ar*H + kc*16 + lc*4) : z4;
            rB[h] = *(const float4*)(Bb + (long)r*H + kc*16 + lc*4);
        }
    };
    auto sts_chunk = [&]() {
        #pragma unroll
        for (int h = 0; h < 2; h++) {
            int r = lr + h*64;
            sA[lc*4+0][r] = rA[h].x; sA[lc*4+1][r] = rA[h].y;
            sA[lc*4+2][r] = rA[h].z; sA[lc*4+3][r] = rA[h].w;
            sB[lc*4+0][r] = rB[h].x; sB[lc*4+1][r] = rB[h].y;
            sB[lc*4+2][r] = rB[h].z; sB[lc*4+3][r] = rB[h].w;
        }
    };

    unsigned long long acc[8][4];
    #pragma unroll
    for (int i = 0; i < 8; i++)
        #pragma unroll
        for (int j = 0; j < 4; j++) acc[i][j] = 0ull;

    ldg_chunk(0);
    sts_chunk();
    __syncthreads();

    for (int kc = 0; kc < 32; kc++) {
        if (kc + 1 < 32) ldg_chunk(kc+1);
        #pragma unroll
        for (int kk = 0; kk < 16; kk++) {
            float4 a0 = *(const float4*)&sA[kk][ty*4];
            float4 a1 = *(const float4*)&sA[kk][64 + ty*4];
            ulonglong2 b0 = *(const ulonglong2*)&sB[kk][tx*4];
            ulonglong2 b1 = *(const ulonglong2*)&sB[kk][64 + tx*4];
            float av[8] = {a0.x,a0.y,a0.z,a0.w, a1.x,a1.y,a1.z,a1.w};
            #pragma unroll
            for (int i = 0; i < 8; i++) {
                unsigned long long ap = packdup(av[i]);
                acc[i][0] = fma2(ap, b0.x, acc[i][0]);
                acc[i][1] = fma2(ap, b0.y, acc[i][1]);
                acc[i][2] = fma2(ap, b1.x, acc[i][2]);
                acc[i][3] = fma2(ap, b1.y, acc[i][3]);
            }
        }
        __syncthreads();
        if (kc + 1 < 32) {
            sts_chunk();
            __syncthreads();
        }
    }

    int k0a = kt*GBN + tx*4;
    int k0b = k0a + 64;
    const float4 bias0 = *(const float4*)(bias + k0a);
    const float4 bias1 = *(const float4*)(bias + k0b);
    #pragma unroll
    for (int i = 0; i < 8; i++) {
        int rloc = (i < 4) ? (ty*4 + i) : (64 + ty*4 + i - 4);
        int ar = row0 + rloc;
        if (ar < LA) {
            const float4 fa0 = *(const float4*)(Ab + (long)ar*H + k0a);
            const float4 fa1 = *(const float4*)(Ab + (long)ar*H + k0b);
            float2 p0 = unpack2(acc[i][0]), p1 = unpack2(acc[i][1]);
            float2 p2 = unpack2(acc[i][2]), p3 = unpack2(acc[i][3]);
            float4 o0 = make_float4(p0.x + bias0.x + fa0.x, p0.y + bias0.y + fa0.y,
                                    p1.x + bias0.z + fa0.z, p1.y + bias0.w + fa0.w);
            float4 o1 = make_float4(p2.x + bias1.x + fa1.x, p2.y + bias1.y + fa1.y,
                                    p3.x + bias1.z + fa1.z, p3.y + bias1.w + fa1.w);
            float* orow = out + ((long)b*LA + ar)*H;
            *(float4*)(orow + k0a) = o0;
            *(float4*)(orow + k0b) = o1;
        }
    }
}

// ---------------- kernel 4: LayerNorm in-place ----------------
__global__ void k_ln(const float* __restrict__ gamma, const float* __restrict__ beta,
                     float* __restrict__ out) {
    __shared__ float ssum[4], ssq[4];
    long row = blockIdx.x;
    int tid = threadIdx.x;
    float4* xr = reinterpret_cast<float4*>(out + row*H);
    float4 v = xr[tid];
    float s  = v.x + v.y + v.z + v.w;
    float sq = v.x*v.x + v.y*v.y + v.z*v.z + v.w*v.w;
    #pragma unroll
    for (int o = 16; o > 0; o >>= 1) {
        s  += __shfl_xor_sync(0xffffffffu, s,  o);
        sq += __shfl_xor_sync(0xffffffffu, sq, o);
    }
    int wid = tid >> 5;
    if ((tid & 31) == 0) { ssum[wid] = s; ssq[wid] = sq; }
    __syncthreads();
    float stot = ssum[0] + ssum[1] + ssum[2] + ssum[3];
    float sqtot = ssq[0] + ssq[1] + ssq[2] + ssq[3];
    float mu = stot * (1.0f/H);
    float var = sqtot * (1.0f/H) - mu*mu;
    float rstd = rsqrtf(var + 1e-5f);
    const float4 g4 = reinterpret_cast<const float4*>(gamma)[tid];
    const float4 b4 = reinterpret_cast<const float4*>(beta)[tid];
    v.x = (v.x - mu)*rstd*g4.x + b4.x;
    v.y = (v.y - mu)*rstd*g4.y + b4.y;
    v.z = (v.z - mu)*rstd*g4.z + b4.z;
    v.w = (v.w - mu)*rstd*g4.w + b4.w;
    xr[tid] = v;
}

// ---------------- launch ----------------
extern "C" void kernel_launch(void* const* d_in, const int* in_sizes, int n_in,
                              void* d_out, int out_size) {
    const float* feat_a = (const float*)d_in[0];
    const float* feat_b = (const float*)d_in[1];
    const float* W      = (const float*)d_in[2];
    const float* bias   = (const float*)d_in[3];
    const float* gamma  = (const float*)d_in[4];
    const float* beta   = (const float*)d_in[5];
    float* out = (float*)d_out;

    static bool attr_done = false;
    if (!attr_done) {
        cudaFuncSetAttribute(k_wgemm_mma, cudaFuncAttributeMaxDynamicSharedMemorySize, WM_SMEM);
        attr_done = true;
    }

    k_bmean_part<<<dim3(8,32), 512>>>(feat_b);
    k_bmean_red<<<32, 512>>>();
    k_bfrag<<<64, 256>>>();
    k_wgemm_mma<<<2048, 256, WM_SMEM>>>(W);
    k_gemm2<<<dim3(4,3,32), 256>>>(feat_a, bias, out);
    k_ln<<<9600, 128>>>(gamma, beta, out);
}

// round 6
// speedup vs baseline: 1.9061x; 1.5312x over previous
#include <cuda_runtime.h>
#include <cstdint>

#define BS 32
#define LA 300
#define LB 1024
#define H  512
#define NROW (H*H)

// ---------------- scratch ----------------
__device__ float g_part[BS*8*H];
__device__ float g_bm[BS*H];          // b_mean [b][e]
__device__ float g_T[(long)BS*NROW];  // [b][k*H+d], values pre-rounded to tf32

// ---------------- helpers ----------------
__device__ __forceinline__ uint32_t f2tf(float f) {
    uint32_t r;
    asm("cvt.rna.tf32.f32 %0, %1;" : "=r"(r) : "f"(f));
    return r;
}
__device__ __forceinline__ void mma_tf32(float* c, uint32_t a0, uint32_t a1,
                                         uint32_t a2, uint32_t a3,
                                         uint32_t b0, uint32_t b1) {
    asm volatile("mma.sync.aligned.m16n8k8.row.col.f32.tf32.tf32.f32 "
                 "{%0,%1,%2,%3}, {%4,%5,%6,%7}, {%8,%9}, {%0,%1,%2,%3};"
                 : "+f"(c[0]), "+f"(c[1]), "+f"(c[2]), "+f"(c[3])
                 : "r"(a0), "r"(a1), "r"(a2), "r"(a3), "r"(b0), "r"(b1));
}

// ---------------- kernel 1: b_mean ----------------
__global__ void k_bmean_part(const float* __restrict__ feat_b) {
    int chunk = blockIdx.x, b = blockIdx.y, d = threadIdx.x;
    const float* p = feat_b + ((long)b*LB + (long)chunk*128)*H + d;
    float s = 0.f;
    #pragma unroll 8
    for (int j = 0; j < 128; j++) s += p[(long)j*H];
    g_part[((long)b*8 + chunk)*H + d] = s;
}
__global__ void k_bmean_red() {
    long idx = (long)blockIdx.x*512 + threadIdx.x;
    long b = idx >> 9, d = idx & 511;
    float s = 0.f;
    #pragma unroll
    for (int c = 0; c < 8; c++) s += g_part[(b*8 + c)*H + d];
    g_bm[idx] = s * (1.0f/1024.0f);
}

// ---------------- kernel 2: T[b][r] = W2d x bm^T via mma.sync tf32 ----------------
// CTA 256 thr / 8 warps, 128 rows. Warp: 16-row slab, N=32, K=512 in 32 chunks of 16.
// A: float4 LDG per row-half per chunk (permuted-k frags). B: bm staged in smem
// [32][528] (tf32-rounded), LDS.128 conflict-free (528/4 mod 8 == 4).
#define SBM 528
#define WM2_SMEM (32*SBM*4 + 16384)   // 67584 + 16384 sD

__global__ void __launch_bounds__(256) k_wgemm_mma(const float* __restrict__ Wg) {
    extern __shared__ char smem[];
    uint32_t* sB = (uint32_t*)smem;            // [32][528] tf32 bits
    float* sD = (float*)(smem + 32*SBM*4);     // [32][128]

    int tid = threadIdx.x;
    int wid = tid >> 5, lane = tid & 31;
    int group = lane >> 2, tg = lane & 3;
    long r0 = (long)blockIdx.x * 128;
    int m0 = wid * 16;

    for (int i = tid; i < 32*512; i += 256) {
        int n = i >> 9, k = i & 511;
        sB[n*SBM + k] = f2tf(g_bm[i]);
    }
    __syncthreads();

    const float4* A0 = (const float4*)(Wg + (r0 + m0 + group)*H) + tg;
    const float4* A1 = A0 + 2*H/4*4/4*0 + (8*H)/4;   // + 8 rows

    float acc[4][4];
    #pragma unroll
    for (int i = 0; i < 4; i++)
        #pragma unroll
        for (int j = 0; j < 4; j++) acc[i][j] = 0.f;

    #pragma unroll 2
    for (int c = 0; c < 32; c++) {
        float4 w0 = __ldg(A0 + c*4);
        float4 w1 = __ldg(A1 + c*4);
        uint32_t ax0 = f2tf(w0.x), ax1 = f2tf(w1.x);
        uint32_t ay0 = f2tf(w0.y), ay1 = f2tf(w1.y);
        uint32_t az0 = f2tf(w0.z), az1 = f2tf(w1.z);
        uint32_t aw0 = f2tf(w0.w), aw1 = f2tf(w1.w);
        #pragma unroll
        for (int nt = 0; nt < 4; nt++) {
            uint4 bv = *(const uint4*)(sB + (nt*8 + group)*SBM + c*16 + tg*4);
            mma_tf32(acc[nt], ax0, ax1, ay0, ay1, bv.x, bv.y);
            mma_tf32(acc[nt], az0, az1, aw0, aw1, bv.z, bv.w);
        }
    }

    // D frag: c0 (row m0+group, col tg*2), c1 (col+1), c2/c3 (+8 rows)
    #pragma unroll
    for (int nt = 0; nt < 4; nt++) {
        int n0 = nt*8 + tg*2;
        int rl = m0 + group;
        sD[(n0  )*128 + rl    ] = acc[nt][0];
        sD[(n0+1)*128 + rl    ] = acc[nt][1];
        sD[(n0  )*128 + rl + 8] = acc[nt][2];
        sD[(n0+1)*128 + rl + 8] = acc[nt][3];
    }
    __syncthreads();
    #pragma unroll
    for (int p = 0; p < 16; p++) {
        int i = p*256 + tid;
        int n = i >> 7, rl = i & 127;
        uint32_t t = f2tf(sD[i]);           // pre-round for gemm2's B operand
        g_T[(long)n*NROW + r0 + rl] = __uint_as_float(t);
    }
}

// ---------------- kernel 3: fused = feat_a @ T^T (+bias +feat_a) via mma ----------
// CTA 256 thr / 8 warps (4 m-slabs x 2 n-halves), tile 64x128, K chunks of 16,
// 4-stage cp.async. A cvt'd to tf32 in-loop; B (g_T) already tf32.
#define G2_STG   12288                 // per-stage bytes: A 64*16*4 + B 128*16*4
#define G2_SMEM  (4*G2_STG)

__global__ void __launch_bounds__(256) k_gemm2(const float* __restrict__ A,
                                               const float* __restrict__ bias,
                                               float* __restrict__ out) {
    extern __shared__ char smem[];
    int b = blockIdx.z, kt = blockIdx.y, mt = blockIdx.x;
    int tid = threadIdx.x;
    int wid = tid >> 5, lane = tid & 31;
    int group = lane >> 2, tg = lane & 3;
    int wm = wid & 3, wc = wid >> 2;
    int row0 = mt * 64;
    const float* Ab = A + (long)b*LA*H;
    const float* Bb = g_T + (long)b*NROW + (long)kt*128*H;

    auto issue = [&](int c) {
        char* st = smem + (c & 3)*G2_STG;
        {   // A: granule tid
            int row = tid >> 2, i = tid & 3;
            const float* src = Ab + (long)(row0 + row)*H + c*16 + i*4;
            unsigned dst = (unsigned)__cvta_generic_to_shared(st + row*64 + i*16);
            int vsz = (row0 + row < LA) ? 16 : 0;
            asm volatile("cp.async.cg.shared.global [%0], [%1], 16, %2;"
                         :: "r"(dst), "l"(src), "r"(vsz));
        }
        #pragma unroll
        for (int q = 0; q < 2; q++) {   // B: 512 granules
            int g2 = q*256 + tid;
            int row = g2 >> 2, i = g2 & 3;
            const float* src = Bb + (long)row*H + c*16 + i*4;
            unsigned dst = (unsigned)__cvta_generic_to_shared(st + 4096 + row*64 + i*16);
            asm volatile("cp.async.cg.shared.global [%0], [%1], 16;"
                         :: "r"(dst), "l"(src));
        }
        asm volatile("cp.async.commit_group;" ::: "memory");
    };

    issue(0); issue(1); issue(2);

    float acc[8][4];
    #pragma unroll
    for (int i = 0; i < 8; i++)
        #pragma unroll
        for (int j = 0; j < 4; j++) acc[i][j] = 0.f;

    for (int c = 0; c < 32; c++) {
        asm volatile("cp.async.wait_group 2;" ::: "memory");
        __syncthreads();
        if (c + 3 < 32) issue(c + 3);

        const char* st = smem + (c & 3)*G2_STG;
        const uint32_t* sA = (const uint32_t*)st;
        const uint32_t* sBt = (const uint32_t*)(st + 4096);

        uint4 a0v = *(const uint4*)(sA + (wm*16 + group)*16 + tg*4);
        uint4 a1v = *(const uint4*)(sA + (wm*16 + group + 8)*16 + tg*4);
        uint32_t ax0 = f2tf(__uint_as_float(a0v.x)), ax1 = f2tf(__uint_as_float(a1v.x));
        uint32_t ay0 = f2tf(__uint_as_float(a0v.y)), ay1 = f2tf(__uint_as_float(a1v.y));
        uint32_t az0 = f2tf(__uint_as_float(a0v.z)), az1 = f2tf(__uint_as_float(a1v.z));
        uint32_t aw0 = f2tf(__uint_as_float(a0v.w)), aw1 = f2tf(__uint_as_float(a1v.w));
        #pragma unroll
        for (int nt = 0; nt < 8; nt++) {
            uint4 bv = *(const uint4*)(sBt + (wc*64 + nt*8 + group)*16 + tg*4);
            mma_tf32(acc[nt], ax0, ax1, ay0, ay1, bv.x, bv.y);
            mma_tf32(acc[nt], az0, az1, aw0, aw1, bv.z, bv.w);
        }
        __syncthreads();
    }

    int grow = row0 + wm*16 + group;
    #pragma unroll
    for (int nt = 0; nt < 8; nt++) {
        int col = kt*128 + wc*64 + nt*8 + tg*2;
        float2 bb = *(const float2*)(bias + col);
        #pragma unroll
        for (int h = 0; h < 2; h++) {
            int r = grow + h*8;
            if (r < LA) {
                float2 fa = *(const float2*)(Ab + (long)r*H + col);
                float2 o;
                o.x = acc[nt][h*2+0] + bb.x + fa.x;
                o.y = acc[nt][h*2+1] + bb.y + fa.y;
                *(float2*)(out + ((long)b*LA + r)*H + col) = o;
            }
        }
    }
}

// ---------------- kernel 4: LayerNorm in-place ----------------
__global__ void k_ln(const float* __restrict__ gamma, const float* __restrict__ beta,
                     float* __restrict__ out) {
    __shared__ float ssum[4], ssq[4];
    long row = blockIdx.x;
    int tid = threadIdx.x;
    float4* xr = reinterpret_cast<float4*>(out + row*H);
    float4 v = xr[tid];
    float s  = v.x + v.y + v.z + v.w;
    float sq = v.x*v.x + v.y*v.y + v.z*v.z + v.w*v.w;
    #pragma unroll
    for (int o = 16; o > 0; o >>= 1) {
        s  += __shfl_xor_sync(0xffffffffu, s,  o);
        sq += __shfl_xor_sync(0xffffffffu, sq, o);
    }
    int wid = tid >> 5;
    if ((tid & 31) == 0) { ssum[wid] = s; ssq[wid] = sq; }
    __syncthreads();
    float stot = ssum[0] + ssum[1] + ssum[2] + ssum[3];
    float sqtot = ssq[0] + ssq[1] + ssq[2] + ssq[3];
    float mu = stot * (1.0f/H);
    float var = sqtot * (1.0f/H) - mu*mu;
    float rstd = rsqrtf(var + 1e-5f);
    const float4 g4 = reinterpret_cast<const float4*>(gamma)[tid];
    const float4 b4 = reinterpret_cast<const float4*>(beta)[tid];
    v.x = (v.x - mu)*rstd*g4.x + b4.x;
    v.y = (v.y - mu)*rstd*g4.y + b4.y;
    v.z = (v.z - mu)*rstd*g4.z + b4.z;
    v.w = (v.w - mu)*rstd*g4.w + b4.w;
    xr[tid] = v;
}

// ---------------- launch ----------------
extern "C" void kernel_launch(void* const* d_in, const int* in_sizes, int n_in,
                              void* d_out, int out_size) {
    const float* feat_a = (const float*)d_in[0];
    const float* feat_b = (const float*)d_in[1];
    const float* W      = (const float*)d_in[2];
    const float* bias   = (const float*)d_in[3];
    const float* gamma  = (const float*)d_in[4];
    const float* beta   = (const float*)d_in[5];
    float* out = (float*)d_out;

    static bool attr_done = false;
    if (!attr_done) {
        cudaFuncSetAttribute(k_wgemm_mma, cudaFuncAttributeMaxDynamicSharedMemorySize, WM2_SMEM);
        cudaFuncSetAttribute(k_gemm2, cudaFuncAttributeMaxDynamicSharedMemorySize, G2_SMEM);
        attr_done = true;
    }

    k_bmean_part<<<dim3(8,32), 512>>>(feat_b);
    k_bmean_red<<<32, 512>>>();
    k_wgemm_mma<<<2048, 256, WM2_SMEM>>>(W);
    k_gemm2<<<dim3(5,4,32), 256, G2_SMEM>>>(feat_a, bias, out);
    k_ln<<<9600, 128>>>(gamma, beta, out);
}